// round 3
// baseline (speedup 1.0000x reference)
#include <cuda_runtime.h>

#define NB 16
#define NN 1024
#define ND 1024
#define NU 512

// Scratch (device globals — no allocation allowed)
__device__ float g_vh[ND];
__device__ float g_vm[ND];
__device__ float g_c;                 // w_out.(b_h+b_m) + b_out
__device__ float g_sH[NB * NN];
__device__ float g_sM[NB * NN];

// ---------------------------------------------------------------------------
// Kernel 1: fold the U dimension, atomic-free.
// Blocks 0..127: block owns d-slice [8*b, 8*b+8). 256 threads = 32 u-rows x
// 8 d-lanes; each thread strides 16 u-steps, then a smem tree reduces the 32
// partials per d. Block 128 computes the scalar constant c.
// ---------------------------------------------------------------------------
__global__ void k_fold(const float* __restrict__ W_h, const float* __restrict__ W_m,
                       const float* __restrict__ w_out, const float* __restrict__ b_h,
                       const float* __restrict__ b_m, const float* __restrict__ b_out) {
    __shared__ float sh[256];
    __shared__ float sm[256];
    const int tid = threadIdx.x;

    if (blockIdx.x < 128) {
        const int dlane = tid & 7;
        const int urow  = tid >> 3;              // 0..31
        const int d = blockIdx.x * 8 + dlane;

        float ah = 0.f, am = 0.f;
        #pragma unroll
        for (int k = 0; k < 16; ++k) {
            const int u = urow + 32 * k;         // covers 0..511
            const float w = __ldg(&w_out[u]);
            ah = fmaf(w, __ldg(&W_h[(size_t)u * ND + d]), ah);
            am = fmaf(w, __ldg(&W_m[(size_t)u * ND + d]), am);
        }
        sh[tid] = ah; sm[tid] = am;
        __syncthreads();
        #pragma unroll
        for (int s = 128; s >= 8; s >>= 1) {
            if (tid < s) { sh[tid] += sh[tid + s]; sm[tid] += sm[tid + s]; }
            __syncthreads();
        }
        if (tid < 8) {
            g_vh[blockIdx.x * 8 + tid] = sh[tid];
            g_vm[blockIdx.x * 8 + tid] = sm[tid];
        }
    } else {
        float acc = 0.f;
        for (int u = tid; u < NU; u += 256)
            acc = fmaf(w_out[u], b_h[u] + b_m[u], acc);
        sh[tid] = acc;
        __syncthreads();
        for (int s = 128; s > 0; s >>= 1) {
            if (tid < s) sh[tid] += sh[tid + s];
            __syncthreads();
        }
        if (tid == 0) g_c = sh[0] + b_out[0];
    }
}

// ---------------------------------------------------------------------------
// Kernel 2: per-token dual dot products. One warp per token row (1024 floats),
// streaming float4 loads (x read exactly once: 64 MiB).
// ---------------------------------------------------------------------------
__global__ void k_rowdots(const float* __restrict__ x) {
    __shared__ float4 svh[ND / 4];
    __shared__ float4 svm[ND / 4];
    const int tid = threadIdx.x;            // 256 threads = 8 warps
    svh[tid] = reinterpret_cast<const float4*>(g_vh)[tid];
    svm[tid] = reinterpret_cast<const float4*>(g_vm)[tid];
    __syncthreads();

    const int warp = tid >> 5, lane = tid & 31;
    const int row = blockIdx.x * 8 + warp;  // 0 .. NB*NN-1
    const float4* x4 = reinterpret_cast<const float4*>(x) + (size_t)row * (ND / 4);

    float ah = 0.f, am = 0.f;
    #pragma unroll
    for (int k = 0; k < 8; ++k) {
        const int idx = k * 32 + lane;
        const float4 xv = __ldcs(&x4[idx]);
        const float4 vh = svh[idx];
        const float4 vm = svm[idx];
        ah = fmaf(xv.x, vh.x, ah); ah = fmaf(xv.y, vh.y, ah);
        ah = fmaf(xv.z, vh.z, ah); ah = fmaf(xv.w, vh.w, ah);
        am = fmaf(xv.x, vm.x, am); am = fmaf(xv.y, vm.y, am);
        am = fmaf(xv.z, vm.z, am); am = fmaf(xv.w, vm.w, am);
    }
    #pragma unroll
    for (int off = 16; off; off >>= 1) {
        ah += __shfl_xor_sync(0xffffffffu, ah, off);
        am += __shfl_xor_sync(0xffffffffu, am, off);
    }
    if (lane == 0) {
        g_sH[row] = ah;
        g_sM[row] = am;
    }
}

// ---------------------------------------------------------------------------
// Kernel 3: outer broadcast-add. scores[b,i,j] = sH[b,i] + sM[b,j] + c.
// Each thread writes 16 contiguous floats (4x STG.128, streaming hint).
// tix = thread's 16-float chunk: 16*tix = b*N*N + i*N + j0.
// ---------------------------------------------------------------------------
__global__ void k_outer(float* __restrict__ out) {
    const unsigned tix = blockIdx.x * 256u + threadIdx.x;   // < 1,048,576
    const unsigned j16 = tix & 63u;        // chunk within row, N/16 = 64
    const unsigned bi  = tix >> 6;         // b*N + i
    const unsigned b   = bi >> 10;         // /N

    const float s = g_sH[bi] + g_c;
    const float4* m4 = reinterpret_cast<const float4*>(g_sM) + (b << 8) + (j16 << 2);
    float4* o4 = reinterpret_cast<float4*>(out) + ((size_t)tix << 2);

    #pragma unroll
    for (int t = 0; t < 4; ++t) {
        const float4 m = __ldg(&m4[t]);
        __stcs(&o4[t], make_float4(s + m.x, s + m.y, s + m.z, s + m.w));
    }
}

extern "C" void kernel_launch(void* const* d_in, const int* in_sizes, int n_in,
                              void* d_out, int out_size) {
    const float* x     = (const float*)d_in[0];
    const float* W_h   = (const float*)d_in[1];
    const float* b_h   = (const float*)d_in[2];
    const float* W_m   = (const float*)d_in[3];
    const float* b_m   = (const float*)d_in[4];
    const float* w_out = (const float*)d_in[5];
    const float* b_out = (const float*)d_in[6];
    float* out = (float*)d_out;

    k_fold<<<129, 256>>>(W_h, W_m, w_out, b_h, b_m, b_out);
    k_rowdots<<<(NB * NN) / 8, 256>>>(x);
    k_outer<<<(NB * NN * NN) / (16 * 256), 256>>>(out);
}

// round 4
// speedup vs baseline: 1.2741x; 1.2741x over previous
#include <cuda_runtime.h>

#define NB 16
#define NN 1024
#define ND 1024
#define NU 512

// Scratch (device globals — no allocation allowed)
__device__ float g_vh[ND];
__device__ float g_vm[ND];
__device__ float g_c;                 // w_out.(b_h+b_m) + b_out
__device__ float g_sH[NB * NN];
__device__ float g_sM[NB * NN];

// ---------------------------------------------------------------------------
// Kernel 1: fold the U dimension, atomic-free.
// Blocks 0..127: block owns d-slice [8*b, 8*b+8). 256 threads = 32 u-rows x
// 8 d-lanes; each thread strides 16 u-steps, then a smem tree reduces the 32
// partials per d. Block 128 computes the scalar constant c.
// ---------------------------------------------------------------------------
__global__ void k_fold(const float* __restrict__ W_h, const float* __restrict__ W_m,
                       const float* __restrict__ w_out, const float* __restrict__ b_h,
                       const float* __restrict__ b_m, const float* __restrict__ b_out) {
    __shared__ float sh[256];
    __shared__ float sm[256];
    const int tid = threadIdx.x;

    if (blockIdx.x < 128) {
        const int dlane = tid & 7;
        const int urow  = tid >> 3;              // 0..31
        const int d = blockIdx.x * 8 + dlane;

        float ah = 0.f, am = 0.f;
        #pragma unroll
        for (int k = 0; k < 16; ++k) {
            const int u = urow + 32 * k;         // covers 0..511
            const float w = __ldg(&w_out[u]);
            ah = fmaf(w, __ldg(&W_h[(size_t)u * ND + d]), ah);
            am = fmaf(w, __ldg(&W_m[(size_t)u * ND + d]), am);
        }
        sh[tid] = ah; sm[tid] = am;
        __syncthreads();
        #pragma unroll
        for (int s = 128; s >= 8; s >>= 1) {
            if (tid < s) { sh[tid] += sh[tid + s]; sm[tid] += sm[tid + s]; }
            __syncthreads();
        }
        if (tid < 8) {
            g_vh[blockIdx.x * 8 + tid] = sh[tid];
            g_vm[blockIdx.x * 8 + tid] = sm[tid];
        }
    } else {
        float acc = 0.f;
        for (int u = tid; u < NU; u += 256)
            acc = fmaf(w_out[u], b_h[u] + b_m[u], acc);
        sh[tid] = acc;
        __syncthreads();
        for (int s = 128; s > 0; s >>= 1) {
            if (tid < s) sh[tid] += sh[tid + s];
            __syncthreads();
        }
        if (tid == 0) g_c = sh[0] + b_out[0];
    }
}

// ---------------------------------------------------------------------------
// Kernel 2: per-token dual dot products. One warp per token row (1024 floats),
// streaming float4 loads (x read exactly once: 64 MiB).
// ---------------------------------------------------------------------------
__global__ void k_rowdots(const float* __restrict__ x) {
    __shared__ float4 svh[ND / 4];
    __shared__ float4 svm[ND / 4];
    const int tid = threadIdx.x;            // 256 threads = 8 warps
    svh[tid] = reinterpret_cast<const float4*>(g_vh)[tid];
    svm[tid] = reinterpret_cast<const float4*>(g_vm)[tid];
    __syncthreads();

    const int warp = tid >> 5, lane = tid & 31;
    const int row = blockIdx.x * 8 + warp;  // 0 .. NB*NN-1
    const float4* x4 = reinterpret_cast<const float4*>(x) + (size_t)row * (ND / 4);

    float ah = 0.f, am = 0.f;
    #pragma unroll
    for (int k = 0; k < 8; ++k) {
        const int idx = k * 32 + lane;
        const float4 xv = __ldcs(&x4[idx]);
        const float4 vh = svh[idx];
        const float4 vm = svm[idx];
        ah = fmaf(xv.x, vh.x, ah); ah = fmaf(xv.y, vh.y, ah);
        ah = fmaf(xv.z, vh.z, ah); ah = fmaf(xv.w, vh.w, ah);
        am = fmaf(xv.x, vm.x, am); am = fmaf(xv.y, vm.y, am);
        am = fmaf(xv.z, vm.z, am); am = fmaf(xv.w, vm.w, am);
    }
    #pragma unroll
    for (int off = 16; off; off >>= 1) {
        ah += __shfl_xor_sync(0xffffffffu, ah, off);
        am += __shfl_xor_sync(0xffffffffu, am, off);
    }
    if (lane == 0) {
        g_sH[row] = ah;
        g_sM[row] = am;
    }
}

// ---------------------------------------------------------------------------
// Kernel 3: outer broadcast-add. scores[b,i,j] = sH[b,i] + sM[b,j] + c.
// Grid-stride, 4 float4 per thread, each warp access fully coalesced
// (32 consecutive float4 = 512B). Normal stores: output stays L2-resident.
// float4 index idx: 4*idx = b*N*N + i*N + j.
// ---------------------------------------------------------------------------
__global__ void k_outer(float* __restrict__ out) {
    const unsigned stride = 2048u * 512u;                 // 1,048,576 float4
    unsigned idx = blockIdx.x * 512u + threadIdx.x;

    #pragma unroll
    for (int t = 0; t < 4; ++t, idx += stride) {
        const unsigned j4 = idx & 255u;    // j/4, N/4 = 256
        const unsigned bi = idx >> 8;      // b*N + i
        const unsigned b  = bi >> 10;      // /N

        const float s = g_sH[bi] + g_c;
        const float4 m = reinterpret_cast<const float4*>(g_sM)[(b << 8) + j4];
        reinterpret_cast<float4*>(out)[idx] =
            make_float4(s + m.x, s + m.y, s + m.z, s + m.w);
    }
}

extern "C" void kernel_launch(void* const* d_in, const int* in_sizes, int n_in,
                              void* d_out, int out_size) {
    const float* x     = (const float*)d_in[0];
    const float* W_h   = (const float*)d_in[1];
    const float* b_h   = (const float*)d_in[2];
    const float* W_m   = (const float*)d_in[3];
    const float* b_m   = (const float*)d_in[4];
    const float* w_out = (const float*)d_in[5];
    const float* b_out = (const float*)d_in[6];
    float* out = (float*)d_out;

    k_fold<<<129, 256>>>(W_h, W_m, w_out, b_h, b_m, b_out);
    k_rowdots<<<(NB * NN) / 8, 256>>>(x);
    k_outer<<<2048, 512>>>(out);
}

// round 5
// speedup vs baseline: 1.3015x; 1.0215x over previous
#include <cuda_runtime.h>

#define NB 16
#define NN 1024
#define ND 1024
#define NU 512

// Scratch (device globals — no allocation allowed).
// g_vh/g_vm are accumulators: zero at module load, and re-zeroed at the end
// of k_outer each call, so every kernel_launch sees them zeroed.
__device__ float g_vh[ND];
__device__ float g_vm[ND];
__device__ float g_c;                 // w_out.(b_h+b_m) + b_out
__device__ float g_sH[NB * NN];
__device__ float g_sM[NB * NN];

// ---------------------------------------------------------------------------
// Kernel 1: fold the U dimension.
// Blocks 0..63: block owns u-chunk [8*b, 8*b+8), sweeps the full 1024-wide d
// row of both W matrices with float4 loads (warp = 512B contiguous), and
// REDG-accumulates its partial into g_vh/g_vm (64 atomics per address).
// Block 64: scalar constant c.
// ---------------------------------------------------------------------------
__global__ void k_fold(const float* __restrict__ W_h, const float* __restrict__ W_m,
                       const float* __restrict__ w_out, const float* __restrict__ b_h,
                       const float* __restrict__ b_m, const float* __restrict__ b_out) {
    const int tid = threadIdx.x;

    if (blockIdx.x < 64) {
        const int u0 = blockIdx.x * 8;
        const float4* Wh4 = reinterpret_cast<const float4*>(W_h) + (size_t)u0 * (ND / 4) + tid;
        const float4* Wm4 = reinterpret_cast<const float4*>(W_m) + (size_t)u0 * (ND / 4) + tid;

        float4 ah = make_float4(0.f, 0.f, 0.f, 0.f);
        float4 am = make_float4(0.f, 0.f, 0.f, 0.f);
        #pragma unroll
        for (int k = 0; k < 8; ++k) {
            const float w = __ldg(&w_out[u0 + k]);
            const float4 h = __ldg(Wh4 + k * (ND / 4));
            const float4 m = __ldg(Wm4 + k * (ND / 4));
            ah.x = fmaf(w, h.x, ah.x); ah.y = fmaf(w, h.y, ah.y);
            ah.z = fmaf(w, h.z, ah.z); ah.w = fmaf(w, h.w, ah.w);
            am.x = fmaf(w, m.x, am.x); am.y = fmaf(w, m.y, am.y);
            am.z = fmaf(w, m.z, am.z); am.w = fmaf(w, m.w, am.w);
        }
        const int d = tid * 4;
        atomicAdd(&g_vh[d + 0], ah.x); atomicAdd(&g_vh[d + 1], ah.y);
        atomicAdd(&g_vh[d + 2], ah.z); atomicAdd(&g_vh[d + 3], ah.w);
        atomicAdd(&g_vm[d + 0], am.x); atomicAdd(&g_vm[d + 1], am.y);
        atomicAdd(&g_vm[d + 2], am.z); atomicAdd(&g_vm[d + 3], am.w);
    } else {
        __shared__ float red[256];
        float acc = 0.f;
        for (int u = tid; u < NU; u += 256)
            acc = fmaf(w_out[u], b_h[u] + b_m[u], acc);
        red[tid] = acc;
        __syncthreads();
        for (int s = 128; s > 0; s >>= 1) {
            if (tid < s) red[tid] += red[tid + s];
            __syncthreads();
        }
        if (tid == 0) g_c = red[0] + b_out[0];
    }
}

// ---------------------------------------------------------------------------
// Kernel 2: per-token dual dot products. One warp per token row (1024 floats),
// streaming float4 loads (x read exactly once: 64 MiB).
// ---------------------------------------------------------------------------
__global__ void k_rowdots(const float* __restrict__ x) {
    __shared__ float4 svh[ND / 4];
    __shared__ float4 svm[ND / 4];
    const int tid = threadIdx.x;            // 256 threads = 8 warps
    svh[tid] = reinterpret_cast<const float4*>(g_vh)[tid];
    svm[tid] = reinterpret_cast<const float4*>(g_vm)[tid];
    __syncthreads();

    const int warp = tid >> 5, lane = tid & 31;
    const int row = blockIdx.x * 8 + warp;  // 0 .. NB*NN-1
    const float4* x4 = reinterpret_cast<const float4*>(x) + (size_t)row * (ND / 4);

    float ah = 0.f, am = 0.f;
    #pragma unroll
    for (int k = 0; k < 8; ++k) {
        const int idx = k * 32 + lane;
        const float4 xv = __ldcs(&x4[idx]);
        const float4 vh = svh[idx];
        const float4 vm = svm[idx];
        ah = fmaf(xv.x, vh.x, ah); ah = fmaf(xv.y, vh.y, ah);
        ah = fmaf(xv.z, vh.z, ah); ah = fmaf(xv.w, vh.w, ah);
        am = fmaf(xv.x, vm.x, am); am = fmaf(xv.y, vm.y, am);
        am = fmaf(xv.z, vm.z, am); am = fmaf(xv.w, vm.w, am);
    }
    #pragma unroll
    for (int off = 16; off; off >>= 1) {
        ah += __shfl_xor_sync(0xffffffffu, ah, off);
        am += __shfl_xor_sync(0xffffffffu, am, off);
    }
    if (lane == 0) {
        g_sH[row] = ah;
        g_sM[row] = am;
    }
}

// ---------------------------------------------------------------------------
// Kernel 3: outer broadcast-add. scores[b,i,j] = sH[b,i] + sM[b,j] + c.
// Grid-stride, 4 float4 per thread, fully coalesced. Tail: re-zero the fold
// accumulators so the next kernel_launch call sees zeros.
// ---------------------------------------------------------------------------
__global__ void k_outer(float* __restrict__ out) {
    const unsigned stride = 2048u * 512u;                 // 1,048,576 float4
    unsigned idx = blockIdx.x * 512u + threadIdx.x;
    const unsigned t0 = idx;

    #pragma unroll
    for (int t = 0; t < 4; ++t, idx += stride) {
        const unsigned j4 = idx & 255u;    // j/4, N/4 = 256
        const unsigned bi = idx >> 8;      // b*N + i
        const unsigned b  = bi >> 10;      // /N

        const float s = g_sH[bi] + g_c;
        const float4 m = reinterpret_cast<const float4*>(g_sM)[(b << 8) + j4];
        reinterpret_cast<float4*>(out)[idx] =
            make_float4(s + m.x, s + m.y, s + m.z, s + m.w);
    }

    if (t0 < 2 * ND) {                     // re-zero accumulators for next call
        if (t0 < ND) g_vh[t0] = 0.f;
        else         g_vm[t0 - ND] = 0.f;
    }
}

extern "C" void kernel_launch(void* const* d_in, const int* in_sizes, int n_in,
                              void* d_out, int out_size) {
    const float* x     = (const float*)d_in[0];
    const float* W_h   = (const float*)d_in[1];
    const float* b_h   = (const float*)d_in[2];
    const float* W_m   = (const float*)d_in[3];
    const float* b_m   = (const float*)d_in[4];
    const float* w_out = (const float*)d_in[5];
    const float* b_out = (const float*)d_in[6];
    float* out = (float*)d_out;

    k_fold<<<65, 256>>>(W_h, W_m, w_out, b_h, b_m, b_out);
    k_rowdots<<<(NB * NN) / 8, 256>>>(x);
    k_outer<<<2048, 512>>>(out);
}